// round 7
// baseline (speedup 1.0000x reference)
#include <cuda_runtime.h>
#include <math.h>

#define B_TOTAL 500000
#define F 100
#define NT 10
#define C 10
#define H 7

#define BLOCK 128
#define ROWS  256                       // rows per block: 2 per thread
#define SMEM_BYTES (ROWS * 50 * 4)      // 51200 B stage -> 4 CTAs/SM

typedef unsigned long long u64;

// ---- packed f32x2 helpers (Blackwell sm_103a) ----
__device__ __forceinline__ u64 pk2(float lo, float hi) {
    u64 r; asm("mov.b64 %0,{%1,%2};" : "=l"(r) : "f"(lo), "f"(hi)); return r;
}
__device__ __forceinline__ void upk2(u64 v, float& lo, float& hi) {
    asm("mov.b64 {%0,%1},%2;" : "=f"(lo), "=f"(hi) : "l"(v));
}
__device__ __forceinline__ u64 ffma2(u64 a, u64 b, u64 c) {
    u64 d; asm("fma.rn.f32x2 %0,%1,%2,%3;" : "=l"(d) : "l"(a), "l"(b), "l"(c)); return d;
}

// Precomputed affine parameters in a __device__ staging block (copied to
// per-CTA shared memory by the main kernel; no constant port involved):
// A_t = Wt_t^T Wt_t - I  (10x10, [t][c][i], i inner)   [0,1000)
// c_t = Wt_t^T hbt_t + vbt_t                           [1000,1100)
// Ah  = Wh^T Wh  ([t][tp], tp inner)                   [1100,1200)
// ch  = Wh^T hbh + vbh                                 [1200,1210)
#define P_A   0
#define P_C   1000
#define P_AH  1100
#define P_CH  1200
#define P_TOT 1216

__device__ __align__(16) float gP[P_TOT];

__global__ void precompute_params(const float* __restrict__ Wt,
                                  const float* __restrict__ hbt,
                                  const float* __restrict__ vbt,
                                  const float* __restrict__ Wh,
                                  const float* __restrict__ hbh,
                                  const float* __restrict__ vbh)
{
    for (int idx = threadIdx.x; idx < 1210; idx += blockDim.x) {
        if (idx < 1000) {                       // A[t][c][i]
            int t = idx / 100, r = idx - t * 100;
            int c = r / 10, i = r - c * 10;
            float a = 0.0f;
            for (int h = 0; h < H; h++)
                a += Wt[(t * H + h) * C + i] * Wt[(t * H + h) * C + c];
            if (i == c) a -= 1.0f;
            gP[P_A + idx] = a;
        } else if (idx < 1100) {                // c_t[t][i]
            int e = idx - 1000;
            int t = e / 10, i = e - t * 10;
            float a = vbt[t * C + i];
            for (int h = 0; h < H; h++)
                a += Wt[(t * H + h) * C + i] * hbt[t * H + h];
            gP[idx] = a;
        } else if (idx < 1200) {                // Ah[t][tp]
            int e = idx - 1100;
            int t = e / 10, tp = e - t * 10;
            float a = 0.0f;
            for (int h = 0; h < H; h++)
                a += Wh[h * NT + tp] * Wh[h * NT + t];
            gP[idx] = a;
        } else {                                // ch[tp]
            int tp = idx - 1200;
            float a = vbh[tp];
            for (int h = 0; h < H; h++)
                a += Wh[h * NT + tp] * hbh[h];
            gP[idx] = a;
        }
    }
}

__global__ __launch_bounds__(BLOCK, 4)
void kitnet_kernel(const float* __restrict__ x,
                   float* __restrict__ out_head,   // [B,NT]
                   float* __restrict__ out_tails)  // [B,NT]
{
    __shared__ __align__(16) float sW[P_TOT];
    extern __shared__ __align__(16) float sX[];    // [ROWS][50] per phase
    u64* s8 = reinterpret_cast<u64*>(sX);          // [ROWS][25]

    const int tid  = threadIdx.x;
    const int lane = tid & 31;
    const int warp = tid >> 5;
    const long long rowBase = (long long)blockIdx.x * ROWS;

    // Parameters into shared (broadcast-read later; no const port).
    for (int i = tid; i < P_TOT; i += BLOCK) sW[i] = gP[i];

    const u64* xg8 = reinterpret_cast<const u64*>(x);

    float tails[2][NT];

    #pragma unroll
    for (int p = 0; p < 2; p++) {
        if (p) __syncthreads();   // phase-0 smem reads complete before restage

        // ---- stage: warp stages rows [64w, 64w+64), lane = pair index ----
        {
            const int r0 = warp * 64;
            #pragma unroll 16
            for (int j = 0; j < 64; j++) {
                const long long gr = rowBase + r0 + j;
                if (lane < 25 && gr < B_TOTAL)
                    s8[(r0 + j) * 25 + lane] = xg8[gr * 50 + p * 25 + lane];
            }
        }
        __syncthreads();

        const u64* rowA = s8 + tid * 25;           // sample A: row tid
        const u64* rowB = s8 + (tid + 128) * 25;   // sample B: row tid+128

        #pragma unroll
        for (int tt = 0; tt < NT / 2; tt++) {
            const int t = p * (NT / 2) + tt;
            const u64* A2 = reinterpret_cast<const u64*>(sW + P_A) + t * 50;
            const u64* c2 = reinterpret_cast<const u64*>(sW + P_C) + t * 5;

            u64 xcA[5], xcB[5];
            #pragma unroll
            for (int j = 0; j < 5; j++) { xcA[j] = rowA[tt * 5 + j]; xcB[j] = rowB[tt * 5 + j]; }

            u64 DA[5], DB[5];
            #pragma unroll
            for (int ip = 0; ip < 5; ip++) { u64 cc = c2[ip]; DA[ip] = cc; DB[ip] = cc; }

            #pragma unroll
            for (int cp = 0; cp < 5; cp++) {
                float aLo, aHi, bLo, bHi;
                upk2(xcA[cp], aLo, aHi);
                upk2(xcB[cp], bLo, bHi);
                const u64 a0 = pk2(aLo, aLo), a1 = pk2(aHi, aHi);
                const u64 b0 = pk2(bLo, bLo), b1 = pk2(bHi, bHi);
                #pragma unroll
                for (int ip = 0; ip < 5; ip++) {
                    const u64 w = A2[cp * 10 + ip];          // col 2cp, shared once
                    DA[ip] = ffma2(a0, w, DA[ip]);
                    DB[ip] = ffma2(b0, w, DB[ip]);
                }
                #pragma unroll
                for (int ip = 0; ip < 5; ip++) {
                    const u64 w = A2[cp * 10 + 5 + ip];      // col 2cp+1
                    DA[ip] = ffma2(a1, w, DA[ip]);
                    DB[ip] = ffma2(b1, w, DB[ip]);
                }
            }

            u64 sA = 0ULL, sB = 0ULL;
            #pragma unroll
            for (int ip = 0; ip < 5; ip++) {
                sA = ffma2(DA[ip], DA[ip], sA);
                sB = ffma2(DB[ip], DB[ip], sB);
            }
            float l0, h0, l1, h1;
            upk2(sA, l0, h0); upk2(sB, l1, h1);
            tails[0][t] = 0.5f * __logf(l0 + h0) - 1.1512925465f;
            tails[1][t] = 0.5f * __logf(l1 + h1) - 1.1512925465f;
        }
    }

    // ---- head: head_out = Ah tails + ch, both samples ----
    const u64* Ah2 = reinterpret_cast<const u64*>(sW + P_AH);
    const u64* ch2 = reinterpret_cast<const u64*>(sW + P_CH);

    u64 hoA[5], hoB[5];
    #pragma unroll
    for (int ip = 0; ip < 5; ip++) { u64 cc = ch2[ip]; hoA[ip] = cc; hoB[ip] = cc; }
    #pragma unroll
    for (int t = 0; t < NT; t++) {
        const u64 ta = pk2(tails[0][t], tails[0][t]);
        const u64 tb = pk2(tails[1][t], tails[1][t]);
        #pragma unroll
        for (int ip = 0; ip < 5; ip++) {
            const u64 w = Ah2[t * 5 + ip];
            hoA[ip] = ffma2(ta, w, hoA[ip]);
            hoB[ip] = ffma2(tb, w, hoB[ip]);
        }
    }

    // ---- output bounce through stage buffer for coalesced stores ----
    __syncthreads();   // all xc reads done before overwriting stage
    {
        u64* slotA = s8 + tid * 25;
        u64* slotB = s8 + (tid + 128) * 25;
        #pragma unroll
        for (int k = 0; k < 5; k++) {
            slotA[k]     = hoA[k];
            slotA[5 + k] = pk2(tails[0][2 * k], tails[0][2 * k + 1]);
            slotB[k]     = hoB[k];
            slotB[5 + k] = pk2(tails[1][2 * k], tails[1][2 * k + 1]);
        }
    }
    __syncthreads();

    {
        u64* oh = reinterpret_cast<u64*>(out_head);
        u64* ot = reinterpret_cast<u64*>(out_tails);
        const long long base = rowBase * 5;                // u64 units
        const long long lim  = (long long)B_TOTAL * 5;
        #pragma unroll
        for (int i = 0; i < (ROWS * 5) / BLOCK; i++) {     // 10 iters
            const int m = i * BLOCK + tid;                 // 0..1279
            const int r = m / 5, j = m - r * 5;
            if (base + m < lim) {
                oh[base + m] = s8[r * 25 + j];
                ot[base + m] = s8[r * 25 + 5 + j];
            }
        }
    }
}

extern "C" void kernel_launch(void* const* d_in, const int* in_sizes, int n_in,
                              void* d_out, int out_size) {
    const float* x = (const float*)d_in[0];
    // d_in[7] = clusters: arange identity by construction -> unused.

    float* out = (float*)d_out;
    float* out_head  = out;                            // [B, NT]
    float* out_tails = out + (long long)B_TOTAL * NT;  // [B, NT]

    static bool init_done = false;
    if (!init_done) {
        cudaFuncSetAttribute(kitnet_kernel,
                             cudaFuncAttributeMaxDynamicSharedMemorySize,
                             SMEM_BYTES);
        init_done = true;
    }

    precompute_params<<<1, 1024>>>((const float*)d_in[1], (const float*)d_in[2],
                                   (const float*)d_in[3], (const float*)d_in[4],
                                   (const float*)d_in[5], (const float*)d_in[6]);

    const int blocks = (B_TOTAL + ROWS - 1) / ROWS;
    kitnet_kernel<<<blocks, BLOCK, SMEM_BYTES>>>(x, out_head, out_tails);
}

// round 8
// speedup vs baseline: 1.0881x; 1.0881x over previous
#include <cuda_runtime.h>
#include <math.h>

#define B_TOTAL 500000
#define F 100
#define NT 10
#define C 10
#define H 7

#define BLOCK 128
#define HALF_F 50                         // columns staged per phase
#define SMEM_BYTES (BLOCK * HALF_F * 4)   // 25600 B dynamic stage

typedef unsigned long long u64;

// ---- packed f32x2 helpers (Blackwell sm_103a) ----
__device__ __forceinline__ u64 pk2(float lo, float hi) {
    u64 r; asm("mov.b64 %0,{%1,%2};" : "=l"(r) : "f"(lo), "f"(hi)); return r;
}
__device__ __forceinline__ void upk2(u64 v, float& lo, float& hi) {
    asm("mov.b64 {%0,%1},%2;" : "=f"(lo), "=f"(hi) : "l"(v));
}
__device__ __forceinline__ u64 ffma2(u64 a, u64 b, u64 c) {
    u64 d; asm("fma.rn.f32x2 %0,%1,%2,%3;" : "=l"(d) : "l"(a), "l"(b), "l"(c)); return d;
}

// Precomputed affine parameters, staged in global, copied per-CTA to shared:
// A_t = Wt_t^T Wt_t - I  (10x10, [t][c][i], i inner)   [0,1000)
// c_t = Wt_t^T hbt_t + vbt_t                           [1000,1100)
// Ah  = Wh^T Wh  ([t][tp], tp inner)                   [1100,1200)
// ch  = Wh^T hbh + vbh                                 [1200,1210)
#define P_A   0
#define P_C   1000
#define P_AH  1100
#define P_CH  1200
#define P_TOT 1216

__device__ __align__(16) float gP[P_TOT];

__global__ void precompute_params(const float* __restrict__ Wt,
                                  const float* __restrict__ hbt,
                                  const float* __restrict__ vbt,
                                  const float* __restrict__ Wh,
                                  const float* __restrict__ hbh,
                                  const float* __restrict__ vbh)
{
    for (int idx = threadIdx.x; idx < 1210; idx += blockDim.x) {
        if (idx < 1000) {                       // A[t][c][i]
            int t = idx / 100, r = idx - t * 100;
            int c = r / 10, i = r - c * 10;
            float a = 0.0f;
            for (int h = 0; h < H; h++)
                a += Wt[(t * H + h) * C + i] * Wt[(t * H + h) * C + c];
            if (i == c) a -= 1.0f;
            gP[P_A + idx] = a;
        } else if (idx < 1100) {                // c_t[t][i]
            int e = idx - 1000;
            int t = e / 10, i = e - t * 10;
            float a = vbt[t * C + i];
            for (int h = 0; h < H; h++)
                a += Wt[(t * H + h) * C + i] * hbt[t * H + h];
            gP[idx] = a;
        } else if (idx < 1200) {                // Ah[t][tp]
            int e = idx - 1100;
            int t = e / 10, tp = e - t * 10;
            float a = 0.0f;
            for (int h = 0; h < H; h++)
                a += Wh[h * NT + tp] * Wh[h * NT + t];
            gP[idx] = a;
        } else {                                // ch[tp]
            int tp = idx - 1200;
            float a = vbh[tp];
            for (int h = 0; h < H; h++)
                a += Wh[h * NT + tp] * hbh[h];
            gP[idx] = a;
        }
    }
}

__global__ __launch_bounds__(BLOCK, 7)
void kitnet_kernel(const float* __restrict__ x,
                   float* __restrict__ out_head,   // [B,NT]
                   float* __restrict__ out_tails)  // [B,NT]
{
    __shared__ __align__(16) float sW[P_TOT];      // weights: broadcast LDS
    extern __shared__ __align__(16) float sX[];    // [BLOCK][50] per phase
    u64* s8 = reinterpret_cast<u64*>(sX);          // [BLOCK][25]

    const int tid  = threadIdx.x;
    const int lane = tid & 31;
    const int warp = tid >> 5;
    const long long rowBase = (long long)blockIdx.x * BLOCK;

    // Weights into shared (read via broadcast LDS, not the constant port).
    for (int i = tid; i < P_TOT; i += BLOCK) sW[i] = gP[i];

    const u64* xrow2 = reinterpret_cast<const u64*>(sX + tid * HALF_F); // 25 pairs
    const u64* xg8 = reinterpret_cast<const u64*>(x);

    const u64* A2all = reinterpret_cast<const u64*>(sW + P_A);
    const u64* c2all = reinterpret_cast<const u64*>(sW + P_C);
    const u64* Ah2   = reinterpret_cast<const u64*>(sW + P_AH);
    const u64* ch2   = reinterpret_cast<const u64*>(sW + P_CH);

    float tails[NT];

    #pragma unroll
    for (int p = 0; p < 2; p++) {
        __syncthreads();   // p=0: sW visible; p=1: phase-0 smem reads complete

        // ---- stage: warp stages its 32 rows, lane = pair index (affine) ----
        {
            const int r0 = warp * 32;
            #pragma unroll 8
            for (int j = 0; j < 32; j++) {
                const int r = r0 + j;
                const long long gr = rowBase + r;
                if (lane < 25 && gr < B_TOTAL)
                    s8[r * 25 + lane] = xg8[gr * 50 + p * 25 + lane];
            }
        }
        __syncthreads();

        // ---- trees 5p..5p+4: d = A_t xc + c_t; tail = 0.5 ln|d|^2 - 0.5 ln10 ----
        #pragma unroll
        for (int tt = 0; tt < NT / 2; tt++) {
            const int t = p * (NT / 2) + tt;
            const u64* A2 = A2all + t * 50;
            const u64* c2 = c2all + t * 5;

            u64 xc[5];
            #pragma unroll
            for (int j = 0; j < 5; j++) xc[j] = xrow2[tt * 5 + j];

            u64 D[5];
            #pragma unroll
            for (int ip = 0; ip < 5; ip++) D[ip] = c2[ip];

            #pragma unroll
            for (int cp = 0; cp < 5; cp++) {
                float lo, hi; upk2(xc[cp], lo, hi);
                const u64 b0 = pk2(lo, lo);
                const u64 b1 = pk2(hi, hi);
                #pragma unroll
                for (int ip = 0; ip < 5; ip++)
                    D[ip] = ffma2(b0, A2[cp * 10 + ip], D[ip]);
                #pragma unroll
                for (int ip = 0; ip < 5; ip++)
                    D[ip] = ffma2(b1, A2[cp * 10 + 5 + ip], D[ip]);
            }

            u64 s2 = 0ULL;
            #pragma unroll
            for (int ip = 0; ip < 5; ip++) s2 = ffma2(D[ip], D[ip], s2);
            float slo, shi; upk2(s2, slo, shi);
            tails[t] = 0.5f * __logf(slo + shi) - 1.1512925465f;
        }
    }

    // ---- head: head_out = Ah tails + ch ----
    u64 ho[5];
    #pragma unroll
    for (int ip = 0; ip < 5; ip++) ho[ip] = ch2[ip];
    #pragma unroll
    for (int t = 0; t < NT; t++) {
        const u64 tb = pk2(tails[t], tails[t]);
        #pragma unroll
        for (int ip = 0; ip < 5; ip++)
            ho[ip] = ffma2(tb, Ah2[t * 5 + ip], ho[ip]);
    }

    u64 tp_[5];
    #pragma unroll
    for (int k = 0; k < 5; k++) tp_[k] = pk2(tails[2 * k], tails[2 * k + 1]);

    // ---- output bounce through smem for coalesced global stores ----
    __syncthreads();   // all xc reads done before overwriting stage
    {
        u64* slot = s8 + tid * 25;
        #pragma unroll
        for (int k = 0; k < 5; k++) slot[k] = ho[k];
        #pragma unroll
        for (int k = 0; k < 5; k++) slot[5 + k] = tp_[k];
    }
    __syncthreads();

    {
        u64* oh = reinterpret_cast<u64*>(out_head);
        u64* ot = reinterpret_cast<u64*>(out_tails);
        const long long base = rowBase * 5;               // u64 units
        const long long lim  = (long long)B_TOTAL * 5;
        #pragma unroll
        for (int i = 0; i < 5; i++) {
            const int m = i * BLOCK + tid;                // 0..639
            const int r = m / 5, j = m - r * 5;
            if (base + m < lim) {
                oh[base + m] = s8[r * 25 + j];
                ot[base + m] = s8[r * 25 + 5 + j];
            }
        }
    }
}

extern "C" void kernel_launch(void* const* d_in, const int* in_sizes, int n_in,
                              void* d_out, int out_size) {
    const float* x = (const float*)d_in[0];
    // d_in[7] = clusters: arange identity by construction -> unused.

    float* out = (float*)d_out;
    float* out_head  = out;                            // [B, NT]
    float* out_tails = out + (long long)B_TOTAL * NT;  // [B, NT]

    static bool init_done = false;
    if (!init_done) {
        cudaFuncSetAttribute(kitnet_kernel,
                             cudaFuncAttributeMaxDynamicSharedMemorySize,
                             SMEM_BYTES);
        init_done = true;
    }

    precompute_params<<<1, 1024>>>((const float*)d_in[1], (const float*)d_in[2],
                                   (const float*)d_in[3], (const float*)d_in[4],
                                   (const float*)d_in[5], (const float*)d_in[6]);

    const int blocks = (B_TOTAL + BLOCK - 1) / BLOCK;
    kitnet_kernel<<<blocks, BLOCK, SMEM_BYTES>>>(x, out_head, out_tails);
}

// round 9
// speedup vs baseline: 1.2186x; 1.1200x over previous
#include <cuda_runtime.h>
#include <math.h>

#define B_TOTAL 500000
#define F 100
#define NT 10
#define C 10
#define H 7

#define BLOCK 128
#define HALF_F 50                         // columns staged per phase
#define SMEM_BYTES (BLOCK * HALF_F * 4)   // 25600 B dynamic stage

typedef unsigned long long u64;

// ---- packed f32x2 helpers (Blackwell sm_103a) ----
__device__ __forceinline__ u64 pk2(float lo, float hi) {
    u64 r; asm("mov.b64 %0,{%1,%2};" : "=l"(r) : "f"(lo), "f"(hi)); return r;
}
__device__ __forceinline__ void upk2(u64 v, float& lo, float& hi) {
    asm("mov.b64 {%0,%1},%2;" : "=f"(lo), "=f"(hi) : "l"(v));
}
__device__ __forceinline__ u64 ffma2(u64 a, u64 b, u64 c) {
    u64 d; asm("fma.rn.f32x2 %0,%1,%2,%3;" : "=l"(d) : "l"(a), "l"(b), "l"(c)); return d;
}

// Precomputed affine parameters:
// A_t = Wt_t^T Wt_t - I  (10x10, [t][c][i], i inner)   [0,1000)
// c_t = Wt_t^T hbt_t + vbt_t                           [1000,1100)
// Ah  = Wh^T Wh  ([t][tp], tp inner)                   [1100,1200)
// ch  = Wh^T hbh + vbh                                 [1200,1210)
#define P_A   0
#define P_C   1000
#define P_AH  1100
#define P_CH  1200
#define P_TOT 1216

__constant__ __align__(16) float cP[P_TOT];
__device__   __align__(16) float gP[P_TOT];

__global__ void precompute_params(const float* __restrict__ Wt,
                                  const float* __restrict__ hbt,
                                  const float* __restrict__ vbt,
                                  const float* __restrict__ Wh,
                                  const float* __restrict__ hbh,
                                  const float* __restrict__ vbh)
{
    for (int idx = threadIdx.x; idx < 1210; idx += blockDim.x) {
        if (idx < 1000) {                       // A[t][c][i]
            int t = idx / 100, r = idx - t * 100;
            int c = r / 10, i = r - c * 10;
            float a = 0.0f;
            for (int h = 0; h < H; h++)
                a += Wt[(t * H + h) * C + i] * Wt[(t * H + h) * C + c];
            if (i == c) a -= 1.0f;
            gP[P_A + idx] = a;
        } else if (idx < 1100) {                // c_t[t][i]
            int e = idx - 1000;
            int t = e / 10, i = e - t * 10;
            float a = vbt[t * C + i];
            for (int h = 0; h < H; h++)
                a += Wt[(t * H + h) * C + i] * hbt[t * H + h];
            gP[idx] = a;
        } else if (idx < 1200) {                // Ah[t][tp]
            int e = idx - 1100;
            int t = e / 10, tp = e - t * 10;
            float a = 0.0f;
            for (int h = 0; h < H; h++)
                a += Wh[h * NT + tp] * Wh[h * NT + t];
            gP[idx] = a;
        } else {                                // ch[tp]
            int tp = idx - 1200;
            float a = vbh[tp];
            for (int h = 0; h < H; h++)
                a += Wh[h * NT + tp] * hbh[h];
            gP[idx] = a;
        }
    }
}

__global__ __launch_bounds__(BLOCK, 8)
void kitnet_kernel(const float* __restrict__ x,
                   float* __restrict__ out_head,   // [B,NT]
                   float* __restrict__ out_tails)  // [B,NT]
{
    // Shared slice of A: columns 6..9 of each tree (cp=3,4), contiguous in gP:
    // floats [t*100+60, t*100+100) -> sAh[t*40 .. t*40+40). 1600 B.
    __shared__ __align__(16) float sAh[NT * 40];
    extern __shared__ __align__(16) float sX[];    // [BLOCK][50] per phase
    u64* s8 = reinterpret_cast<u64*>(sX);          // [BLOCK][25]

    const int tid  = threadIdx.x;
    const int lane = tid & 31;
    const int warp = tid >> 5;
    const long long rowBase = (long long)blockIdx.x * BLOCK;

    // Load the shared slice (once per CTA).
    for (int i = tid; i < NT * 40; i += BLOCK) {
        int t = i / 40, r = i - t * 40;
        sAh[i] = gP[P_A + t * 100 + 60 + r];
    }

    const u64* xrow2 = reinterpret_cast<const u64*>(sX + tid * HALF_F); // 25 pairs
    const u64* xg8 = reinterpret_cast<const u64*>(x);

    const u64* cA2  = reinterpret_cast<const u64*>(cP + P_A);
    const u64* cC2  = reinterpret_cast<const u64*>(cP + P_C);
    const u64* cAh2 = reinterpret_cast<const u64*>(cP + P_AH);
    const u64* cCh2 = reinterpret_cast<const u64*>(cP + P_CH);
    const u64* sA2  = reinterpret_cast<const u64*>(sAh);   // [t][20 u64]

    float tails[NT];

    #pragma unroll
    for (int p = 0; p < 2; p++) {
        __syncthreads();   // p=0: sAh visible; p=1: phase-0 smem reads complete

        // ---- stage: warp stages its 32 rows, lane = pair index (affine) ----
        {
            const int r0 = warp * 32;
            #pragma unroll 8
            for (int j = 0; j < 32; j++) {
                const int r = r0 + j;
                const long long gr = rowBase + r;
                if (lane < 25 && gr < B_TOTAL)
                    s8[r * 25 + lane] = xg8[gr * 50 + p * 25 + lane];
            }
        }
        __syncthreads();

        // prefetch first tree's xc
        u64 xc[5];
        #pragma unroll
        for (int j = 0; j < 5; j++) xc[j] = xrow2[j];

        #pragma unroll
        for (int tt = 0; tt < NT / 2; tt++) {
            const int t = p * (NT / 2) + tt;

            // prefetch next tree's xc while this tree computes
            u64 xn[5];
            if (tt < NT / 2 - 1) {
                #pragma unroll
                for (int j = 0; j < 5; j++) xn[j] = xrow2[(tt + 1) * 5 + j];
            }

            u64 D[5];
            #pragma unroll
            for (int ip = 0; ip < 5; ip++) D[ip] = cC2[t * 5 + ip];

            #pragma unroll
            for (int cp = 0; cp < 5; cp++) {
                float lo, hi; upk2(xc[cp], lo, hi);
                const u64 b0 = pk2(lo, lo);
                const u64 b1 = pk2(hi, hi);
                // cp<3 -> constant port; cp>=3 -> shared slice (compile-time select)
                const u64* w0 = (cp < 3) ? (cA2 + t * 50 + cp * 10)
                                         : (sA2 + t * 20 + (cp - 3) * 10);
                #pragma unroll
                for (int ip = 0; ip < 5; ip++)
                    D[ip] = ffma2(b0, w0[ip], D[ip]);
                #pragma unroll
                for (int ip = 0; ip < 5; ip++)
                    D[ip] = ffma2(b1, w0[5 + ip], D[ip]);
            }

            u64 s2 = 0ULL;
            #pragma unroll
            for (int ip = 0; ip < 5; ip++) s2 = ffma2(D[ip], D[ip], s2);
            float slo, shi; upk2(s2, slo, shi);
            tails[t] = 0.5f * __logf(slo + shi) - 1.1512925465f;

            if (tt < NT / 2 - 1) {
                #pragma unroll
                for (int j = 0; j < 5; j++) xc[j] = xn[j];
            }
        }
    }

    // ---- head: head_out = Ah tails + ch (constant port) ----
    u64 ho[5];
    #pragma unroll
    for (int ip = 0; ip < 5; ip++) ho[ip] = cCh2[ip];
    #pragma unroll
    for (int t = 0; t < NT; t++) {
        const u64 tb = pk2(tails[t], tails[t]);
        #pragma unroll
        for (int ip = 0; ip < 5; ip++)
            ho[ip] = ffma2(tb, cAh2[t * 5 + ip], ho[ip]);
    }

    u64 tp_[5];
    #pragma unroll
    for (int k = 0; k < 5; k++) tp_[k] = pk2(tails[2 * k], tails[2 * k + 1]);

    // ---- output bounce through smem for coalesced global stores ----
    __syncthreads();   // all xc reads done before overwriting stage
    {
        u64* slot = s8 + tid * 25;
        #pragma unroll
        for (int k = 0; k < 5; k++) slot[k] = ho[k];
        #pragma unroll
        for (int k = 0; k < 5; k++) slot[5 + k] = tp_[k];
    }
    __syncthreads();

    {
        u64* oh = reinterpret_cast<u64*>(out_head);
        u64* ot = reinterpret_cast<u64*>(out_tails);
        const long long base = rowBase * 5;               // u64 units
        const long long lim  = (long long)B_TOTAL * 5;
        #pragma unroll
        for (int i = 0; i < 5; i++) {
            const int m = i * BLOCK + tid;                // 0..639
            const int r = m / 5, j = m - r * 5;
            if (base + m < lim) {
                oh[base + m] = s8[r * 25 + j];
                ot[base + m] = s8[r * 25 + 5 + j];
            }
        }
    }
}

extern "C" void kernel_launch(void* const* d_in, const int* in_sizes, int n_in,
                              void* d_out, int out_size) {
    const float* x = (const float*)d_in[0];
    // d_in[7] = clusters: arange identity by construction -> unused.

    float* out = (float*)d_out;
    float* out_head  = out;                            // [B, NT]
    float* out_tails = out + (long long)B_TOTAL * NT;  // [B, NT]

    static void* cP_addr = nullptr;
    static void* gP_addr = nullptr;
    static bool init_done = false;
    if (!init_done) {
        cudaGetSymbolAddress(&cP_addr, cP);
        cudaGetSymbolAddress(&gP_addr, gP);
        cudaFuncSetAttribute(kitnet_kernel,
                             cudaFuncAttributeMaxDynamicSharedMemorySize,
                             SMEM_BYTES);
        init_done = true;
    }

    precompute_params<<<1, 1024>>>((const float*)d_in[1], (const float*)d_in[2],
                                   (const float*)d_in[3], (const float*)d_in[4],
                                   (const float*)d_in[5], (const float*)d_in[6]);
    cudaMemcpyAsync(cP_addr, gP_addr, P_TOT * 4, cudaMemcpyDeviceToDevice);

    const int blocks = (B_TOTAL + BLOCK - 1) / BLOCK;
    kitnet_kernel<<<blocks, BLOCK, SMEM_BYTES>>>(x, out_head, out_tails);
}

// round 10
// speedup vs baseline: 1.4401x; 1.1817x over previous
#include <cuda_runtime.h>
#include <math.h>

#define B_TOTAL 500000
#define F 100
#define NT 10
#define C 10
#define H 7

#define BLOCK 128
#define PAIRS 25                              // u64 pairs per phase per row
#define SMEM_BYTES (2 * BLOCK * PAIRS * 8)    // 51200 B: double-buffered stage

typedef unsigned long long u64;

// ---- packed f32x2 helpers (Blackwell sm_103a) ----
__device__ __forceinline__ u64 pk2(float lo, float hi) {
    u64 r; asm("mov.b64 %0,{%1,%2};" : "=l"(r) : "f"(lo), "f"(hi)); return r;
}
__device__ __forceinline__ void upk2(u64 v, float& lo, float& hi) {
    asm("mov.b64 {%0,%1},%2;" : "=f"(lo), "=f"(hi) : "l"(v));
}
__device__ __forceinline__ u64 ffma2(u64 a, u64 b, u64 c) {
    u64 d; asm("fma.rn.f32x2 %0,%1,%2,%3;" : "=l"(d) : "l"(a), "l"(b), "l"(c)); return d;
}

// Precomputed affine parameters (R6 layout, full constant):
// A_t = Wt_t^T Wt_t - I  (10x10, [t][c][i], i inner)   [0,1000)
// c_t = Wt_t^T hbt_t + vbt_t                           [1000,1100)
// Ah  = Wh^T Wh  ([t][tp], tp inner)                   [1100,1200)
// ch  = Wh^T hbh + vbh                                 [1200,1210)
#define P_A   0
#define P_C   1000
#define P_AH  1100
#define P_CH  1200
#define P_TOT 1216

__constant__ __align__(16) float cP[P_TOT];
__device__   __align__(16) float gP[P_TOT];

__global__ void precompute_params(const float* __restrict__ Wt,
                                  const float* __restrict__ hbt,
                                  const float* __restrict__ vbt,
                                  const float* __restrict__ Wh,
                                  const float* __restrict__ hbh,
                                  const float* __restrict__ vbh)
{
    for (int idx = threadIdx.x; idx < 1210; idx += blockDim.x) {
        if (idx < 1000) {                       // A[t][c][i]
            int t = idx / 100, r = idx - t * 100;
            int c = r / 10, i = r - c * 10;
            float a = 0.0f;
            for (int h = 0; h < H; h++)
                a += Wt[(t * H + h) * C + i] * Wt[(t * H + h) * C + c];
            if (i == c) a -= 1.0f;
            gP[P_A + idx] = a;
        } else if (idx < 1100) {                // c_t[t][i]
            int e = idx - 1000;
            int t = e / 10, i = e - t * 10;
            float a = vbt[t * C + i];
            for (int h = 0; h < H; h++)
                a += Wt[(t * H + h) * C + i] * hbt[t * H + h];
            gP[idx] = a;
        } else if (idx < 1200) {                // Ah[t][tp]
            int e = idx - 1100;
            int t = e / 10, tp = e - t * 10;
            float a = 0.0f;
            for (int h = 0; h < H; h++)
                a += Wh[h * NT + tp] * Wh[h * NT + t];
            gP[idx] = a;
        } else {                                // ch[tp]
            int tp = idx - 1200;
            float a = vbh[tp];
            for (int h = 0; h < H; h++)
                a += Wh[h * NT + tp] * hbh[h];
            gP[idx] = a;
        }
    }
}

__device__ __forceinline__ void cp_async8(void* smem_dst, const void* gmem_src) {
    unsigned s = (unsigned)__cvta_generic_to_shared(smem_dst);
    asm volatile("cp.async.ca.shared.global [%0], [%1], 8;"
                 :: "r"(s), "l"(gmem_src) : "memory");
}

__device__ __forceinline__ void compute_phase(const u64* __restrict__ row,
                                              int p, float* tails)
{
    const u64* cA2 = reinterpret_cast<const u64*>(cP + P_A);
    const u64* cC2 = reinterpret_cast<const u64*>(cP + P_C);

    #pragma unroll
    for (int tt = 0; tt < NT / 2; tt++) {
        const int t = p * (NT / 2) + tt;

        u64 xc[5];
        #pragma unroll
        for (int j = 0; j < 5; j++) xc[j] = row[tt * 5 + j];

        u64 D[5];
        #pragma unroll
        for (int ip = 0; ip < 5; ip++) D[ip] = cC2[t * 5 + ip];

        #pragma unroll
        for (int cp = 0; cp < 5; cp++) {
            float lo, hi; upk2(xc[cp], lo, hi);
            const u64 b0 = pk2(lo, lo);
            const u64 b1 = pk2(hi, hi);
            #pragma unroll
            for (int ip = 0; ip < 5; ip++)
                D[ip] = ffma2(b0, cA2[t * 50 + cp * 10 + ip], D[ip]);
            #pragma unroll
            for (int ip = 0; ip < 5; ip++)
                D[ip] = ffma2(b1, cA2[t * 50 + cp * 10 + 5 + ip], D[ip]);
        }

        u64 s2 = 0ULL;
        #pragma unroll
        for (int ip = 0; ip < 5; ip++) s2 = ffma2(D[ip], D[ip], s2);
        float slo, shi; upk2(s2, slo, shi);
        tails[t] = 0.5f * __logf(slo + shi) - 1.1512925465f;  // log(sqrt(sse/10))
    }
}

__global__ __launch_bounds__(BLOCK, 4)
void kitnet_kernel(const float* __restrict__ x,
                   float* __restrict__ out_head,   // [B,NT]
                   float* __restrict__ out_tails)  // [B,NT]
{
    extern __shared__ __align__(16) u64 s8[];   // [2][BLOCK][25]
    u64* buf0 = s8;
    u64* buf1 = s8 + BLOCK * PAIRS;

    const int tid  = threadIdx.x;
    const int lane = tid & 31;
    const int warp = tid >> 5;
    const long long rowBase = (long long)blockIdx.x * BLOCK;

    const u64* xg8 = reinterpret_cast<const u64*>(x);

    // ---- fire both staging phases up-front as two cp.async groups ----
    // Warp stages rows [32w, 32w+32); lane = pair index within the half-row.
    {
        const int r0 = warp * 32;
        if (lane < PAIRS) {
            #pragma unroll 8
            for (int j = 0; j < 32; j++) {
                const long long gr = rowBase + r0 + j;
                if (gr < B_TOTAL)
                    cp_async8(&buf0[(r0 + j) * PAIRS + lane],
                              xg8 + gr * 50 + lane);
            }
        }
        asm volatile("cp.async.commit_group;" ::: "memory");
        if (lane < PAIRS) {
            #pragma unroll 8
            for (int j = 0; j < 32; j++) {
                const long long gr = rowBase + r0 + j;
                if (gr < B_TOTAL)
                    cp_async8(&buf1[(r0 + j) * PAIRS + lane],
                              xg8 + gr * 50 + PAIRS + lane);
            }
        }
        asm volatile("cp.async.commit_group;" ::: "memory");
    }

    float tails[NT];

    // ---- phase 0: trees 0..4 (phase-1 bytes still streaming) ----
    asm volatile("cp.async.wait_group 1;" ::: "memory");
    __syncthreads();
    compute_phase(buf0 + tid * PAIRS, 0, tails);

    // ---- phase 1: trees 5..9 ----
    asm volatile("cp.async.wait_group 0;" ::: "memory");
    __syncthreads();   // also: all buf0 reads are complete past this point
    compute_phase(buf1 + tid * PAIRS, 1, tails);

    // ---- head: head_out = Ah tails + ch (constant port) ----
    const u64* cAh2 = reinterpret_cast<const u64*>(cP + P_AH);
    const u64* cCh2 = reinterpret_cast<const u64*>(cP + P_CH);

    u64 ho[5];
    #pragma unroll
    for (int ip = 0; ip < 5; ip++) ho[ip] = cCh2[ip];
    #pragma unroll
    for (int t = 0; t < NT; t++) {
        const u64 tb = pk2(tails[t], tails[t]);
        #pragma unroll
        for (int ip = 0; ip < 5; ip++)
            ho[ip] = ffma2(tb, cAh2[t * 5 + ip], ho[ip]);
    }

    u64 tp_[5];
    #pragma unroll
    for (int k = 0; k < 5; k++) tp_[k] = pk2(tails[2 * k], tails[2 * k + 1]);

    // ---- output bounce through buf0 (free after 2nd barrier) ----
    {
        u64* slot = buf0 + tid * PAIRS;
        #pragma unroll
        for (int k = 0; k < 5; k++) slot[k] = ho[k];
        #pragma unroll
        for (int k = 0; k < 5; k++) slot[5 + k] = tp_[k];
    }
    __syncthreads();

    {
        u64* oh = reinterpret_cast<u64*>(out_head);
        u64* ot = reinterpret_cast<u64*>(out_tails);
        const long long base = rowBase * 5;               // u64 units
        const long long lim  = (long long)B_TOTAL * 5;
        #pragma unroll
        for (int i = 0; i < 5; i++) {
            const int m = i * BLOCK + tid;                // 0..639
            const int r = m / 5, j = m - r * 5;
            if (base + m < lim) {
                oh[base + m] = buf0[r * PAIRS + j];
                ot[base + m] = buf0[r * PAIRS + 5 + j];
            }
        }
    }
}

extern "C" void kernel_launch(void* const* d_in, const int* in_sizes, int n_in,
                              void* d_out, int out_size) {
    const float* x = (const float*)d_in[0];
    // d_in[7] = clusters: arange identity by construction -> unused.

    float* out = (float*)d_out;
    float* out_head  = out;                            // [B, NT]
    float* out_tails = out + (long long)B_TOTAL * NT;  // [B, NT]

    static void* cP_addr = nullptr;
    static void* gP_addr = nullptr;
    static bool init_done = false;
    if (!init_done) {
        cudaGetSymbolAddress(&cP_addr, cP);
        cudaGetSymbolAddress(&gP_addr, gP);
        cudaFuncSetAttribute(kitnet_kernel,
                             cudaFuncAttributeMaxDynamicSharedMemorySize,
                             SMEM_BYTES);
        init_done = true;
    }

    precompute_params<<<1, 1024>>>((const float*)d_in[1], (const float*)d_in[2],
                                   (const float*)d_in[3], (const float*)d_in[4],
                                   (const float*)d_in[5], (const float*)d_in[6]);
    cudaMemcpyAsync(cP_addr, gP_addr, P_TOT * 4, cudaMemcpyDeviceToDevice);

    const int blocks = (B_TOTAL + BLOCK - 1) / BLOCK;
    kitnet_kernel<<<blocks, BLOCK, SMEM_BYTES>>>(x, out_head, out_tails);
}